// round 3
// baseline (speedup 1.0000x reference)
#include <cuda_runtime.h>
#include <cuda_bf16.h>

#define B     4
#define LQ    128
#define LK    1024
#define D     512
#define DV    512
#define UNITS 256

typedef unsigned long long ull;

// Scratch (device globals — no allocation allowed)
__device__ float g_qp[B * LQ * UNITS];
__device__ float g_kp[B * LK * UNITS];
__device__ float g_sc[B * LQ * LK];     // raw scores (unmasked region only)
__device__ int   g_vlen[B];

__device__ __forceinline__ float tanh_fast(float x) {
    float y;
    asm("tanh.approx.f32 %0, %1;" : "=f"(y) : "f"(x));
    return y;
}
__device__ __forceinline__ ull ffma2(ull a, ull b, ull c) {
    ull d;
    asm("fma.rn.f32x2 %0, %1, %2, %3;" : "=l"(d) : "l"(a), "l"(b), "l"(c));
    return d;
}
__device__ __forceinline__ float2 unpack2(ull v) {
    float2 f;
    asm("mov.b64 {%0, %1}, %2;" : "=f"(f.x), "=f"(f.y) : "l"(v));
    return f;
}

// ---------------------------------------------------------------------------
// 1) Fused projection GEMM for q AND k (+ vlen decode).
//    rows [0,512): g_qp = query @ Wq^T ; rows [512,4608): g_kp = key @ Wk^T
//    BM=64, BN=64, BK=16, 128 threads, 4x8 microtile, FFMA2 with
//    A duplicated in shared -> zero packing MOVs. Double-buffered smem.
//    Grid = 72 x 4 = 288 CTAs.
// ---------------------------------------------------------------------------
__global__ __launch_bounds__(128) void proj_kernel(
    const float* __restrict__ query, const float* __restrict__ key,
    const float* __restrict__ Wq,    const float* __restrict__ Wk,
    const void*  __restrict__ vl)
{
    if (blockIdx.x == 0 && blockIdx.y == 0 && threadIdx.x == 0) {
        const long long* l = (const long long*)vl;
        const int*       w = (const int*)vl;
        bool ok64 = true;
        #pragma unroll
        for (int i = 0; i < B; i++) {
            long long x = l[i];
            if (x < 1 || x > LK) ok64 = false;
        }
        #pragma unroll
        for (int i = 0; i < B; i++) g_vlen[i] = ok64 ? (int)l[i] : w[i];
    }

    __shared__ float As[2][16][132];   // A duplicated: As[kk][2m]=As[kk][2m+1]
    __shared__ float Bs[2][16][64];    // B natural

    int tid = threadIdx.x;
    int ty  = tid >> 3;                // 0..15 -> rows ty*4
    int tx  = tid & 7;                 // 0..7  -> cols tx*8

    int mg = blockIdx.x * 64;
    int n0 = blockIdx.y * 64;

    const float *X, *W;
    float* Y;
    int m0;
    if (mg < B * LQ) { X = query; W = Wq; Y = g_qp; m0 = mg; }
    else             { X = key;   W = Wk; Y = g_kp; m0 = mg - B * LQ; }

    // staging indices: each thread loads 8 k-floats of one X row + one W row
    int sm = tid >> 1;                 // 0..63 row
    int sk = (tid & 1) * 8;            // k offset 0 or 8

    const float* xrow = X + (size_t)(m0 + sm) * D + sk;
    const float* wrow = W + (size_t)(n0 + sm) * D + sk;

    float4 xr0, xr1, wr0, wr1;

    // preload tile 0
    xr0 = *(const float4*)(xrow);
    xr1 = *(const float4*)(xrow + 4);
    wr0 = *(const float4*)(wrow);
    wr1 = *(const float4*)(wrow + 4);
    {
        float xv[8] = {xr0.x,xr0.y,xr0.z,xr0.w,xr1.x,xr1.y,xr1.z,xr1.w};
        float wv[8] = {wr0.x,wr0.y,wr0.z,wr0.w,wr1.x,wr1.y,wr1.z,wr1.w};
        #pragma unroll
        for (int i = 0; i < 8; i++) {
            As[0][sk + i][2 * sm]     = xv[i];
            As[0][sk + i][2 * sm + 1] = xv[i];
            Bs[0][sk + i][sm]         = wv[i];
        }
    }
    __syncthreads();

    ull acc[4][4] = {};

    const int NT = D / 16;             // 32 k-tiles
    for (int t = 0; t < NT; t++) {
        int buf = t & 1;
        if (t + 1 < NT) {
            const float* xn = xrow + (t + 1) * 16;
            const float* wn = wrow + (t + 1) * 16;
            xr0 = *(const float4*)(xn);
            xr1 = *(const float4*)(xn + 4);
            wr0 = *(const float4*)(wn);
            wr1 = *(const float4*)(wn + 4);
        }

        #pragma unroll
        for (int kk = 0; kk < 16; kk++) {
            longlong2 a0 = *(const longlong2*)&As[buf][kk][ty * 8];
            longlong2 a1 = *(const longlong2*)&As[buf][kk][ty * 8 + 4];
            longlong2 b0 = *(const longlong2*)&Bs[buf][kk][tx * 8];
            longlong2 b1 = *(const longlong2*)&Bs[buf][kk][tx * 8 + 4];
            ull aa[4] = {(ull)a0.x, (ull)a0.y, (ull)a1.x, (ull)a1.y};
            ull bb[4] = {(ull)b0.x, (ull)b0.y, (ull)b1.x, (ull)b1.y};
            #pragma unroll
            for (int i = 0; i < 4; i++)
                #pragma unroll
                for (int j = 0; j < 4; j++)
                    acc[i][j] = ffma2(aa[i], bb[j], acc[i][j]);
        }

        if (t + 1 < NT) {
            int nb = buf ^ 1;
            float xv[8] = {xr0.x,xr0.y,xr0.z,xr0.w,xr1.x,xr1.y,xr1.z,xr1.w};
            float wv[8] = {wr0.x,wr0.y,wr0.z,wr0.w,wr1.x,wr1.y,wr1.z,wr1.w};
            #pragma unroll
            for (int i = 0; i < 8; i++) {
                As[nb][sk + i][2 * sm]     = xv[i];
                As[nb][sk + i][2 * sm + 1] = xv[i];
                Bs[nb][sk + i][sm]         = wv[i];
            }
        }
        __syncthreads();
    }

    #pragma unroll
    for (int i = 0; i < 4; i++) {
        float* dst = Y + (size_t)(m0 + ty * 4 + i) * UNITS + n0 + tx * 8;
        float2 r0 = unpack2(acc[i][0]);
        float2 r1 = unpack2(acc[i][1]);
        float2 r2 = unpack2(acc[i][2]);
        float2 r3 = unpack2(acc[i][3]);
        *(float4*)(dst)     = make_float4(r0.x, r0.y, r1.x, r1.y);
        *(float4*)(dst + 4) = make_float4(r2.x, r2.y, r3.x, r3.y);
    }
}

// ---------------------------------------------------------------------------
// 2) Scores: one thread per k, no shuffles. Grid (LK/256, LQ/8, B) = 256 CTAs
//    of 256 threads. qp rows + v staged in shared (broadcast reads).
//    s[b,q,k] = sum_u v[u] * tanh(qp[b,q,u] + kp[b,k,u]).  MUFU-bound.
// ---------------------------------------------------------------------------
__global__ __launch_bounds__(256) void score_kernel(const float* __restrict__ vvec)
{
    __shared__ float qs[8][UNITS];
    __shared__ float vs[UNITS];

    int b    = blockIdx.z;
    int q0   = blockIdx.y * 8;
    int k0   = blockIdx.x * 256;
    int vlen = g_vlen[b];
    if (k0 >= vlen) return;

    int tid = threadIdx.x;

    vs[tid] = vvec[tid];
    #pragma unroll
    for (int qq = 0; qq < 8; qq++)
        qs[qq][tid] = g_qp[(size_t)(b * LQ + q0 + qq) * UNITS + tid];
    __syncthreads();

    int k = k0 + tid;
    if (k >= vlen) return;

    const float* kr = g_kp + (size_t)(b * LK + k) * UNITS;

    float acc[8] = {0.f, 0.f, 0.f, 0.f, 0.f, 0.f, 0.f, 0.f};

    #pragma unroll 4
    for (int u = 0; u < UNITS; u += 4) {
        float4 kv = *(const float4*)(kr + u);
        float4 vv = *(const float4*)&vs[u];
        #pragma unroll
        for (int qq = 0; qq < 8; qq++) {
            float4 qv = *(const float4*)&qs[qq][u];
            acc[qq] = fmaf(vv.x, tanh_fast(qv.x + kv.x), acc[qq]);
            acc[qq] = fmaf(vv.y, tanh_fast(qv.y + kv.y), acc[qq]);
            acc[qq] = fmaf(vv.z, tanh_fast(qv.z + kv.z), acc[qq]);
            acc[qq] = fmaf(vv.w, tanh_fast(qv.w + kv.w), acc[qq]);
        }
    }

    float* scb = g_sc + (size_t)(b * LQ + q0) * LK + k;
    #pragma unroll
    for (int qq = 0; qq < 8; qq++)
        scb[(size_t)qq * LK] = acc[qq];
}

// ---------------------------------------------------------------------------
// 3) Fused softmax + output GEMM.
//    CTA: (b, 32 q-rows, 64 v-cols). Phase 1: per-row max & 1/sum over
//    [0,vlen). Phase 2: GEMM over k<kend=ceil32(vlen), staging
//    p = exp(s - rowmax) (0 beyond vlen); 1/sum applied in epilogue.
// ---------------------------------------------------------------------------
__global__ __launch_bounds__(256) void out_kernel(
    const float* __restrict__ value, float* __restrict__ out)
{
    __shared__ float As[32][34];
    __shared__ float Bs[32][64];
    __shared__ float rmax[32], rinv[32];

    int b    = blockIdx.z;
    int m0   = blockIdx.x * 32;
    int n0   = blockIdx.y * 64;
    int vlen = g_vlen[b];
    int kend = (vlen + 31) & ~31;

    const float* S = g_sc  + (size_t)(b * LQ + m0) * LK;
    const float* V = value + (size_t)b * LK * DV;

    int tid  = threadIdx.x;
    int lane = tid & 31;
    int wid  = tid >> 5;

    for (int r = wid; r < 32; r += 8) {
        const float* srow = S + (size_t)r * LK;
        float m = -3.0e38f;
        for (int k = lane; k < vlen; k += 32) m = fmaxf(m, srow[k]);
        #pragma unroll
        for (int off = 16; off > 0; off >>= 1)
            m = fmaxf(m, __shfl_xor_sync(0xFFFFFFFFu, m, off));
        float s = 0.f;
        for (int k = lane; k < vlen; k += 32) s += __expf(srow[k] - m);
        #pragma unroll
        for (int off = 16; off > 0; off >>= 1)
            s += __shfl_xor_sync(0xFFFFFFFFu, s, off);
        if (lane == 0) { rmax[r] = m; rinv[r] = 1.0f / s; }
    }
    __syncthreads();

    int ty = tid >> 4, tx = tid & 15;
    int am = tid >> 3, ak = (tid & 7) * 4;
    int bk = tid >> 3, bn = (tid & 7) * 8;

    ull acc[2][2] = {};

    for (int k0 = 0; k0 < kend; k0 += 32) {
        float4 sv = *(const float4*)(S + (size_t)am * LK + k0 + ak);
        float mr = rmax[am];
        int kg = k0 + ak;
        As[ak + 0][am] = (kg + 0 < vlen) ? __expf(sv.x - mr) : 0.f;
        As[ak + 1][am] = (kg + 1 < vlen) ? __expf(sv.y - mr) : 0.f;
        As[ak + 2][am] = (kg + 2 < vlen) ? __expf(sv.z - mr) : 0.f;
        As[ak + 3][am] = (kg + 3 < vlen) ? __expf(sv.w - mr) : 0.f;

        const float* vp = V + (size_t)(k0 + bk) * DV + n0 + bn;
        *(float4*)&Bs[bk][bn]     = *(const float4*)(vp);
        *(float4*)&Bs[bk][bn + 4] = *(const float4*)(vp + 4);
        __syncthreads();

        #pragma unroll
        for (int kk = 0; kk < 32; kk++) {
            float2 af = *(const float2*)&As[kk][ty * 2];
            ull ap0, ap1;
            asm("mov.b64 %0, {%1, %1};" : "=l"(ap0) : "f"(af.x));
            asm("mov.b64 %0, {%1, %1};" : "=l"(ap1) : "f"(af.y));
            longlong2 bv = *(const longlong2*)&Bs[kk][tx * 4];
            acc[0][0] = ffma2(ap0, (ull)bv.x, acc[0][0]);
            acc[0][1] = ffma2(ap0, (ull)bv.y, acc[0][1]);
            acc[1][0] = ffma2(ap1, (ull)bv.x, acc[1][0]);
            acc[1][1] = ffma2(ap1, (ull)bv.y, acc[1][1]);
        }
        __syncthreads();
    }

    #pragma unroll
    for (int i = 0; i < 2; i++) {
        int r = ty * 2 + i;
        float inv = rinv[r];
        float2 r0 = unpack2(acc[i][0]);
        float2 r1 = unpack2(acc[i][1]);
        *(float4*)(out + (size_t)(b * LQ + m0 + r) * DV + n0 + tx * 4) =
            make_float4(r0.x * inv, r0.y * inv, r1.x * inv, r1.y * inv);
    }
}

// ---------------------------------------------------------------------------
// kernel_launch — inputs: query, key, value, valid_len, W_q, W_k, v
// ---------------------------------------------------------------------------
extern "C" void kernel_launch(void* const* d_in, const int* in_sizes, int n_in,
                              void* d_out, int out_size)
{
    const float* query = (const float*)d_in[0];
    const float* key   = (const float*)d_in[1];
    const float* value = (const float*)d_in[2];
    const void*  vlen  = d_in[3];
    const float* W_q   = (const float*)d_in[4];
    const float* W_k   = (const float*)d_in[5];
    const float* vvec  = (const float*)d_in[6];
    float* out = (float*)d_out;

    // 1) fused q+k projection (+ vlen decode): 72 x 4 = 288 CTAs, 128 thr
    proj_kernel<<<dim3((B * LQ + B * LK) / 64, UNITS / 64), 128>>>(
        query, key, W_q, W_k, vlen);

    // 2) scores: 4 x 16 x 4 = 256 CTAs (masked tiles exit)
    score_kernel<<<dim3(LK / 256, LQ / 8, B), 256>>>(vvec);

    // 3) fused softmax + output GEMM: 4 x 8 x 4 = 128 CTAs
    out_kernel<<<dim3(LQ / 32, DV / 64, B), 256>>>(value, out);
}

// round 4
// speedup vs baseline: 1.1022x; 1.1022x over previous
#include <cuda_runtime.h>
#include <cuda_bf16.h>

#define B     4
#define LQ    128
#define LK    1024
#define D     512
#define DV    512
#define UNITS 256

typedef unsigned long long ull;

// Scratch (device globals — no allocation allowed)
__device__ float g_qp [B * LQ * UNITS];        // natural [b*LQ+q][u]
__device__ float g_kpT[B * UNITS * LK];        // transposed [b][u][k]
__device__ float g_sc [B * LQ * LK];           // raw scores (unmasked region)
__device__ int   g_vlen[B];

__device__ __forceinline__ float tanh_fast(float x) {
    float y;
    asm("tanh.approx.f32 %0, %1;" : "=f"(y) : "f"(x));
    return y;
}
__device__ __forceinline__ ull ffma2(ull a, ull b, ull c) {
    ull d;
    asm("fma.rn.f32x2 %0, %1, %2, %3;" : "=l"(d) : "l"(a), "l"(b), "l"(c));
    return d;
}
__device__ __forceinline__ ull dup2(float x) {
    ull r;
    asm("mov.b64 %0, {%1, %1};" : "=l"(r) : "f"(x));
    return r;
}
__device__ __forceinline__ float2 unpack2(ull v) {
    float2 f;
    asm("mov.b64 {%0, %1}, %2;" : "=f"(f.x), "=f"(f.y) : "l"(v));
    return f;
}

// B-tile swizzle: row of 128 floats stored as 2 sections of 64; each section:
// [8 groups x float4 (cols 8g..8g+3)][8 groups x float4 (cols 8g+4..8g+7)]
// -> a warp's 8 lane-groups read 16-B lines at 16-B stride = conflict-free.
__device__ __forceinline__ int bswz(int n) {
    int sec = n >> 6, r = n & 63;
    return sec * 64 + ((r >> 2) & 1) * 32 + (r >> 3) * 4 + (r & 3);
}

// ---------------------------------------------------------------------------
// 1) Fused projection GEMM (+ vlen decode).
//    rows [0,512): g_qp = query @ Wq^T (natural)
//    rows [512,4608): g_kpT = (key @ Wk^T) transposed to [b][u][k]
//    CTA 64m x 128n, 128 threads, warp tile 32x64, lane 4x8, 8x8/thread.
//    Double-buffered smem, FFMA2 mainloop. Grid = 72 x 2 = 144 CTAs.
// ---------------------------------------------------------------------------
__global__ __launch_bounds__(128) void proj_kernel(
    const float* __restrict__ query, const float* __restrict__ key,
    const float* __restrict__ Wq,    const float* __restrict__ Wk,
    const void*  __restrict__ vl)
{
    if (blockIdx.x == 0 && blockIdx.y == 0 && threadIdx.x == 0) {
        const long long* l = (const long long*)vl;
        const int*       w = (const int*)vl;
        bool ok64 = true;
        #pragma unroll
        for (int i = 0; i < B; i++) {
            long long x = l[i];
            if (x < 1 || x > LK) ok64 = false;
        }
        #pragma unroll
        for (int i = 0; i < B; i++) g_vlen[i] = ok64 ? (int)l[i] : w[i];
    }

    __shared__ float As[2][16][68];    // natural [kk][m]
    __shared__ float Bs[2][16][132];   // swizzled rows (bswz)

    int tid  = threadIdx.x;
    int lane = tid & 31;
    int wrp  = tid >> 5;
    int warpM = wrp >> 1, warpN = wrp & 1;
    int lm = lane >> 3;                // 0..3
    int ln = lane & 7;                 // 0..7
    int rm = warpM * 32 + lm * 8;      // thread rows rm..rm+7
    int cn = warpN * 64 + ln * 8;      // thread cols cn..cn+7

    int mg = blockIdx.x * 64;
    int n0 = blockIdx.y * 128;

    const float *X, *W;
    bool is_q = (mg < B * LQ);
    int m0;
    if (is_q) { X = query; W = Wq; m0 = mg; }
    else      { X = key;   W = Wk; m0 = mg - B * LQ; }

    // staging: A: 2 threads/row (8 k-floats each); B: 1 thread/row (16 k)
    int sm = tid >> 1;
    int sk = (tid & 1) * 8;
    const float* xrow = X + (size_t)(m0 + sm) * D + sk;
    const float* wrow = W + (size_t)(n0 + tid) * D;
    int bo = bswz(tid);

    float4 xr0, xr1, w0, w1, w2, w3;
    xr0 = *(const float4*)(xrow);
    xr1 = *(const float4*)(xrow + 4);
    w0 = *(const float4*)(wrow);
    w1 = *(const float4*)(wrow + 4);
    w2 = *(const float4*)(wrow + 8);
    w3 = *(const float4*)(wrow + 12);
    {
        float xv[8] = {xr0.x,xr0.y,xr0.z,xr0.w,xr1.x,xr1.y,xr1.z,xr1.w};
        float wv[16] = {w0.x,w0.y,w0.z,w0.w, w1.x,w1.y,w1.z,w1.w,
                        w2.x,w2.y,w2.z,w2.w, w3.x,w3.y,w3.z,w3.w};
        #pragma unroll
        for (int i = 0; i < 8; i++) As[0][sk + i][sm] = xv[i];
        #pragma unroll
        for (int i = 0; i < 16; i++) Bs[0][i][bo] = wv[i];
    }
    __syncthreads();

    ull acc[8][4] = {};

    const int NT = D / 16;
    for (int t = 0; t < NT; t++) {
        int buf = t & 1;
        if (t + 1 < NT) {
            const float* xn = xrow + (t + 1) * 16;
            const float* wn = wrow + (t + 1) * 16;
            xr0 = *(const float4*)(xn);
            xr1 = *(const float4*)(xn + 4);
            w0 = *(const float4*)(wn);
            w1 = *(const float4*)(wn + 4);
            w2 = *(const float4*)(wn + 8);
            w3 = *(const float4*)(wn + 12);
        }

        #pragma unroll
        for (int kk = 0; kk < 16; kk++) {
            float4 a0 = *(const float4*)&As[buf][kk][rm];
            float4 a1 = *(const float4*)&As[buf][kk][rm + 4];
            // B: section warpN, lo half at +ln*4, hi half at +32+ln*4
            longlong2 b0 = *(const longlong2*)&Bs[buf][kk][warpN * 64 + ln * 4];
            longlong2 b1 = *(const longlong2*)&Bs[buf][kk][warpN * 64 + 32 + ln * 4];
            ull aa[8];
            aa[0] = dup2(a0.x); aa[1] = dup2(a0.y);
            aa[2] = dup2(a0.z); aa[3] = dup2(a0.w);
            aa[4] = dup2(a1.x); aa[5] = dup2(a1.y);
            aa[6] = dup2(a1.z); aa[7] = dup2(a1.w);
            ull bb[4] = {(ull)b0.x, (ull)b0.y, (ull)b1.x, (ull)b1.y};
            #pragma unroll
            for (int i = 0; i < 8; i++)
                #pragma unroll
                for (int j = 0; j < 4; j++)
                    acc[i][j] = ffma2(aa[i], bb[j], acc[i][j]);
        }

        if (t + 1 < NT) {
            int nb = buf ^ 1;
            float xv[8] = {xr0.x,xr0.y,xr0.z,xr0.w,xr1.x,xr1.y,xr1.z,xr1.w};
            float wv[16] = {w0.x,w0.y,w0.z,w0.w, w1.x,w1.y,w1.z,w1.w,
                            w2.x,w2.y,w2.z,w2.w, w3.x,w3.y,w3.z,w3.w};
            #pragma unroll
            for (int i = 0; i < 8; i++) As[nb][sk + i][sm] = xv[i];
            #pragma unroll
            for (int i = 0; i < 16; i++) Bs[nb][i][bo] = wv[i];
        }
        __syncthreads();
    }

    if (is_q) {
        // natural row-major write to g_qp
        #pragma unroll
        for (int i = 0; i < 8; i++) {
            float* dst = g_qp + (size_t)(m0 + rm + i) * UNITS + n0 + cn;
            float2 r0 = unpack2(acc[i][0]);
            float2 r1 = unpack2(acc[i][1]);
            float2 r2 = unpack2(acc[i][2]);
            float2 r3 = unpack2(acc[i][3]);
            *(float4*)(dst)     = make_float4(r0.x, r0.y, r1.x, r1.y);
            *(float4*)(dst + 4) = make_float4(r2.x, r2.y, r3.x, r3.y);
        }
    } else {
        // transposed write to g_kpT[b][u][k]
        float colv[8][8];
        #pragma unroll
        for (int i = 0; i < 8; i++)
            #pragma unroll
            for (int jp = 0; jp < 4; jp++) {
                float2 p = unpack2(acc[i][jp]);
                colv[2 * jp][i]     = p.x;
                colv[2 * jp + 1][i] = p.y;
            }
        int bb_ = m0 >> 10;
        int kbase = (m0 & 1023) + rm;
        #pragma unroll
        for (int c = 0; c < 8; c++) {
            float* dst = g_kpT + (size_t)(bb_ * UNITS + n0 + cn + c) * LK + kbase;
            *(float4*)(dst)     = make_float4(colv[c][0], colv[c][1], colv[c][2], colv[c][3]);
            *(float4*)(dst + 4) = make_float4(colv[c][4], colv[c][5], colv[c][6], colv[c][7]);
        }
    }
}

// ---------------------------------------------------------------------------
// 2) Scores: thread owns a k-quad (float4, coalesced via kpT), 4 q-rows.
//    Grid (LK/512, LQ/4, B) = 256 CTAs, 128 threads. MUFU.TANH-bound.
//    s[b,q,k] = sum_u v[u] * tanh(qp[b,q,u] + kpT[b,u,k]).
// ---------------------------------------------------------------------------
__global__ __launch_bounds__(128) void score_kernel(const float* __restrict__ vvec)
{
    __shared__ float qs[4][UNITS];
    __shared__ float vs[UNITS];

    int b    = blockIdx.z;
    int q0   = blockIdx.y * 4;
    int k0   = blockIdx.x * 512;
    int vlen = g_vlen[b];
    if (k0 >= vlen) return;

    int tid = threadIdx.x;
    #pragma unroll
    for (int i = 0; i < 8; i++) {
        int idx = tid + i * 128;           // 0..1023
        qs[idx >> 8][idx & 255] =
            g_qp[(size_t)(b * LQ + q0 + (idx >> 8)) * UNITS + (idx & 255)];
    }
    vs[tid] = vvec[tid];
    vs[tid + 128] = vvec[tid + 128];       // UNITS=256
    __syncthreads();

    int k = k0 + tid * 4;
    if (k >= vlen) return;

    const float* kc = g_kpT + (size_t)b * UNITS * LK + k;

    float4 a0 = {0,0,0,0}, a1 = {0,0,0,0}, a2 = {0,0,0,0}, a3 = {0,0,0,0};

    #pragma unroll 2
    for (int u4 = 0; u4 < UNITS; u4 += 4) {
        float4 vv  = *(const float4*)&vs[u4];
        float4 q0v = *(const float4*)&qs[0][u4];
        float4 q1v = *(const float4*)&qs[1][u4];
        float4 q2v = *(const float4*)&qs[2][u4];
        float4 q3v = *(const float4*)&qs[3][u4];
        #pragma unroll
        for (int s = 0; s < 4; s++) {
            float4 kv = *(const float4*)(kc + (size_t)(u4 + s) * LK);
            float vu = (s == 0) ? vv.x : (s == 1) ? vv.y : (s == 2) ? vv.z : vv.w;
            float qu0 = (s == 0) ? q0v.x : (s == 1) ? q0v.y : (s == 2) ? q0v.z : q0v.w;
            float qu1 = (s == 0) ? q1v.x : (s == 1) ? q1v.y : (s == 2) ? q1v.z : q1v.w;
            float qu2 = (s == 0) ? q2v.x : (s == 1) ? q2v.y : (s == 2) ? q2v.z : q2v.w;
            float qu3 = (s == 0) ? q3v.x : (s == 1) ? q3v.y : (s == 2) ? q3v.z : q3v.w;
            a0.x = fmaf(vu, tanh_fast(qu0 + kv.x), a0.x);
            a0.y = fmaf(vu, tanh_fast(qu0 + kv.y), a0.y);
            a0.z = fmaf(vu, tanh_fast(qu0 + kv.z), a0.z);
            a0.w = fmaf(vu, tanh_fast(qu0 + kv.w), a0.w);
            a1.x = fmaf(vu, tanh_fast(qu1 + kv.x), a1.x);
            a1.y = fmaf(vu, tanh_fast(qu1 + kv.y), a1.y);
            a1.z = fmaf(vu, tanh_fast(qu1 + kv.z), a1.z);
            a1.w = fmaf(vu, tanh_fast(qu1 + kv.w), a1.w);
            a2.x = fmaf(vu, tanh_fast(qu2 + kv.x), a2.x);
            a2.y = fmaf(vu, tanh_fast(qu2 + kv.y), a2.y);
            a2.z = fmaf(vu, tanh_fast(qu2 + kv.z), a2.z);
            a2.w = fmaf(vu, tanh_fast(qu2 + kv.w), a2.w);
            a3.x = fmaf(vu, tanh_fast(qu3 + kv.x), a3.x);
            a3.y = fmaf(vu, tanh_fast(qu3 + kv.y), a3.y);
            a3.z = fmaf(vu, tanh_fast(qu3 + kv.z), a3.z);
            a3.w = fmaf(vu, tanh_fast(qu3 + kv.w), a3.w);
        }
    }

    float* sp = g_sc + (size_t)(b * LQ + q0) * LK + k;
    *(float4*)(sp)              = a0;
    *(float4*)(sp + LK)         = a1;
    *(float4*)(sp + 2 * LK)     = a2;
    *(float4*)(sp + 3 * LK)     = a3;
}

// ---------------------------------------------------------------------------
// 3) Fused softmax + output GEMM (unchanged from R2).
// ---------------------------------------------------------------------------
__global__ __launch_bounds__(256) void out_kernel(
    const float* __restrict__ value, float* __restrict__ out)
{
    __shared__ float As[32][34];
    __shared__ float Bs[32][64];
    __shared__ float rmax[32], rinv[32];

    int b    = blockIdx.z;
    int m0   = blockIdx.x * 32;
    int n0   = blockIdx.y * 64;
    int vlen = g_vlen[b];
    int kend = (vlen + 31) & ~31;

    const float* S = g_sc  + (size_t)(b * LQ + m0) * LK;
    const float* V = value + (size_t)b * LK * DV;

    int tid  = threadIdx.x;
    int lane = tid & 31;
    int wid  = tid >> 5;

    for (int r = wid; r < 32; r += 8) {
        const float* srow = S + (size_t)r * LK;
        float m = -3.0e38f;
        for (int k = lane; k < vlen; k += 32) m = fmaxf(m, srow[k]);
        #pragma unroll
        for (int off = 16; off > 0; off >>= 1)
            m = fmaxf(m, __shfl_xor_sync(0xFFFFFFFFu, m, off));
        float s = 0.f;
        for (int k = lane; k < vlen; k += 32) s += __expf(srow[k] - m);
        #pragma unroll
        for (int off = 16; off > 0; off >>= 1)
            s += __shfl_xor_sync(0xFFFFFFFFu, s, off);
        if (lane == 0) { rmax[r] = m; rinv[r] = 1.0f / s; }
    }
    __syncthreads();

    int ty = tid >> 4, tx = tid & 15;
    int am = tid >> 3, ak = (tid & 7) * 4;
    int bk = tid >> 3, bn = (tid & 7) * 8;

    ull acc[2][2] = {};

    for (int k0 = 0; k0 < kend; k0 += 32) {
        float4 sv = *(const float4*)(S + (size_t)am * LK + k0 + ak);
        float mr = rmax[am];
        int kg = k0 + ak;
        As[ak + 0][am] = (kg + 0 < vlen) ? __expf(sv.x - mr) : 0.f;
        As[ak + 1][am] = (kg + 1 < vlen) ? __expf(sv.y - mr) : 0.f;
        As[ak + 2][am] = (kg + 2 < vlen) ? __expf(sv.z - mr) : 0.f;
        As[ak + 3][am] = (kg + 3 < vlen) ? __expf(sv.w - mr) : 0.f;

        const float* vp = V + (size_t)(k0 + bk) * DV + n0 + bn;
        *(float4*)&Bs[bk][bn]     = *(const float4*)(vp);
        *(float4*)&Bs[bk][bn + 4] = *(const float4*)(vp + 4);
        __syncthreads();

        #pragma unroll
        for (int kk = 0; kk < 32; kk++) {
            float2 af = *(const float2*)&As[kk][ty * 2];
            ull ap0 = dup2(af.x);
            ull ap1 = dup2(af.y);
            longlong2 bv = *(const longlong2*)&Bs[kk][tx * 4];
            acc[0][0] = ffma2(ap0, (ull)bv.x, acc[0][0]);
            acc[0][1] = ffma2(ap0, (ull)bv.y, acc[0][1]);
            acc[1][0] = ffma2(ap1, (ull)bv.x, acc[1][0]);
            acc[1][1] = ffma2(ap1, (ull)bv.y, acc[1][1]);
        }
        __syncthreads();
    }

    #pragma unroll
    for (int i = 0; i < 2; i++) {
        int r = ty * 2 + i;
        float inv = rinv[r];
        float2 r0 = unpack2(acc[i][0]);
        float2 r1 = unpack2(acc[i][1]);
        *(float4*)(out + (size_t)(b * LQ + m0 + r) * DV + n0 + tx * 4) =
            make_float4(r0.x * inv, r0.y * inv, r1.x * inv, r1.y * inv);
    }
}

// ---------------------------------------------------------------------------
// kernel_launch — inputs: query, key, value, valid_len, W_q, W_k, v
// ---------------------------------------------------------------------------
extern "C" void kernel_launch(void* const* d_in, const int* in_sizes, int n_in,
                              void* d_out, int out_size)
{
    const float* query = (const float*)d_in[0];
    const float* key   = (const float*)d_in[1];
    const float* value = (const float*)d_in[2];
    const void*  vlen  = d_in[3];
    const float* W_q   = (const float*)d_in[4];
    const float* W_k   = (const float*)d_in[5];
    const float* vvec  = (const float*)d_in[6];
    float* out = (float*)d_out;

    // 1) fused q+k projection (+ vlen decode): 72 x 2 = 144 CTAs, 128 thr
    proj_kernel<<<dim3((B * LQ + B * LK) / 64, UNITS / 128), 128>>>(
        query, key, W_q, W_k, vlen);

    // 2) scores: 2 x 32 x 4 = 256 CTAs, 128 thr (masked tiles exit)
    score_kernel<<<dim3(LK / 512, LQ / 4, B), 128>>>(vvec);

    // 3) fused softmax + output GEMM: 4 x 8 x 4 = 128 CTAs
    out_kernel<<<dim3(LQ / 32, DV / 64, B), 256>>>(value, out);
}

// round 5
// speedup vs baseline: 1.2547x; 1.1384x over previous
#include <cuda_runtime.h>
#include <cuda_bf16.h>

#define B     4
#define LQ    128
#define LK    1024
#define D     512
#define DV    512
#define UNITS 256

typedef unsigned long long ull;

// Scratch (device globals — no allocation allowed)
__device__ float g_qp[B * LQ * UNITS];         // [b*LQ+q][u]
__device__ float g_kp[B * LK * UNITS];         // [b*LK+k][u]
__device__ float g_sc[B * LQ * LK];            // raw scores (unmasked region)
__device__ int   g_vlen[B];

__device__ __forceinline__ float tanh_fast(float x) {
    float y;
    asm("tanh.approx.f32 %0, %1;" : "=f"(y) : "f"(x));
    return y;
}
__device__ __forceinline__ ull ffma2(ull a, ull b, ull c) {
    ull d;
    asm("fma.rn.f32x2 %0, %1, %2, %3;" : "=l"(d) : "l"(a), "l"(b), "l"(c));
    return d;
}
__device__ __forceinline__ ull dup2(float x) {
    ull r;
    asm("mov.b64 %0, {%1, %1};" : "=l"(r) : "f"(x));
    return r;
}
__device__ __forceinline__ float2 unpack2(ull v) {
    float2 f;
    asm("mov.b64 {%0, %1}, %2;" : "=f"(f.x), "=f"(f.y) : "l"(v));
    return f;
}

// swizzle for 64-col B rows: col c -> ((c>>2)&1)*32 + (c>>3)*4 + (c&3)
// lane-groups then read 16B-stride float4s = all 32 banks, conflict-free.
__device__ __forceinline__ int bswz64(int c) {
    return ((c >> 2) & 1) * 32 + (c >> 3) * 4 + (c & 3);
}

// ---------------------------------------------------------------------------
// 1) Fused projection GEMM (+ vlen decode + per-batch k-tile skipping).
//    rows [0,512): g_qp = query @ Wq^T ; rows [512,4608): g_kp = key @ Wk^T
//    CTA 64m x 64n, 128 threads, thread tile 4x8 (FFMA2), double-buffered.
//    Grid 72 x 4 = 288 CTAs (2 CTAs/SM, 2 warps/SMSP). k-tiles fully beyond
//    vlen[b] exit immediately (their kp rows are never read downstream).
// ---------------------------------------------------------------------------
__global__ __launch_bounds__(128) void proj_kernel(
    const float* __restrict__ query, const float* __restrict__ key,
    const float* __restrict__ Wq,    const float* __restrict__ Wk,
    const void*  __restrict__ vl)
{
    // local (uniform) vlen decode
    const long long* l = (const long long*)vl;
    const int*       w = (const int*)vl;
    bool ok64 = true;
    #pragma unroll
    for (int i = 0; i < B; i++) {
        long long x = l[i];
        if (x < 1 || x > LK) ok64 = false;
    }
    if (blockIdx.x == 0 && blockIdx.y == 0 && threadIdx.x == 0) {
        #pragma unroll
        for (int i = 0; i < B; i++) g_vlen[i] = ok64 ? (int)l[i] : w[i];
    }

    int mg = blockIdx.x * 64;
    int n0 = blockIdx.y * 64;
    bool is_q = (mg < B * LQ);

    const float *X, *W;
    float* Y;
    int m0;
    if (is_q) { X = query; W = Wq; Y = g_qp; m0 = mg; }
    else {
        m0 = mg - B * LQ;
        int bb = m0 >> 10;
        int krow = m0 & 1023;
        int vb = ok64 ? (int)l[bb] : w[bb];
        if (krow >= vb) return;          // uniform exit: tile fully masked
        X = key; W = Wk; Y = g_kp;
    }

    __shared__ float As[2][16][68];      // natural [kk][m]
    __shared__ float Bs[2][16][68];      // swizzled columns (bswz64)

    int tid = threadIdx.x;
    int tm  = tid >> 3;                  // 0..15 -> rows tm*4
    int tn  = tid & 7;                   // 0..7  -> cols tn*8

    // staging: 2 threads per row, 8 k-floats each
    int sm = tid >> 1;
    int sk = (tid & 1) * 8;
    const float* xrow = X + (size_t)(m0 + sm) * D + sk;
    const float* wrow = W + (size_t)(n0 + sm) * D + sk;
    int bo = bswz64(sm);

    float4 xr0, xr1, wr0, wr1;
    xr0 = *(const float4*)(xrow);
    xr1 = *(const float4*)(xrow + 4);
    wr0 = *(const float4*)(wrow);
    wr1 = *(const float4*)(wrow + 4);
    {
        float xv[8] = {xr0.x,xr0.y,xr0.z,xr0.w,xr1.x,xr1.y,xr1.z,xr1.w};
        float wv[8] = {wr0.x,wr0.y,wr0.z,wr0.w,wr1.x,wr1.y,wr1.z,wr1.w};
        #pragma unroll
        for (int i = 0; i < 8; i++) {
            As[0][sk + i][sm] = xv[i];
            Bs[0][sk + i][bo] = wv[i];
        }
    }
    __syncthreads();

    ull acc[4][4] = {};

    const int NT = D / 16;               // 32 k-tiles
    for (int t = 0; t < NT; t++) {
        int buf = t & 1;
        if (t + 1 < NT) {
            const float* xn = xrow + (t + 1) * 16;
            const float* wn = wrow + (t + 1) * 16;
            xr0 = *(const float4*)(xn);
            xr1 = *(const float4*)(xn + 4);
            wr0 = *(const float4*)(wn);
            wr1 = *(const float4*)(wn + 4);
        }

        #pragma unroll
        for (int kk = 0; kk < 16; kk++) {
            float4 av = *(const float4*)&As[buf][kk][tm * 4];
            longlong2 b0 = *(const longlong2*)&Bs[buf][kk][tn * 4];
            longlong2 b1 = *(const longlong2*)&Bs[buf][kk][32 + tn * 4];
            ull aa[4];
            aa[0] = dup2(av.x); aa[1] = dup2(av.y);
            aa[2] = dup2(av.z); aa[3] = dup2(av.w);
            ull bb[4] = {(ull)b0.x, (ull)b0.y, (ull)b1.x, (ull)b1.y};
            #pragma unroll
            for (int i = 0; i < 4; i++)
                #pragma unroll
                for (int j = 0; j < 4; j++)
                    acc[i][j] = ffma2(aa[i], bb[j], acc[i][j]);
        }

        if (t + 1 < NT) {
            int nb = buf ^ 1;
            float xv[8] = {xr0.x,xr0.y,xr0.z,xr0.w,xr1.x,xr1.y,xr1.z,xr1.w};
            float wv[8] = {wr0.x,wr0.y,wr0.z,wr0.w,wr1.x,wr1.y,wr1.z,wr1.w};
            #pragma unroll
            for (int i = 0; i < 8; i++) {
                As[nb][sk + i][sm] = xv[i];
                Bs[nb][sk + i][bo] = wv[i];
            }
        }
        __syncthreads();
    }

    #pragma unroll
    for (int i = 0; i < 4; i++) {
        float* dst = Y + (size_t)(m0 + tm * 4 + i) * UNITS + n0 + tn * 8;
        float2 r0 = unpack2(acc[i][0]);
        float2 r1 = unpack2(acc[i][1]);
        float2 r2 = unpack2(acc[i][2]);
        float2 r3 = unpack2(acc[i][3]);
        *(float4*)(dst)     = make_float4(r0.x, r0.y, r1.x, r1.y);
        *(float4*)(dst + 4) = make_float4(r2.x, r2.y, r3.x, r3.y);
    }
}

// ---------------------------------------------------------------------------
// 2) Scores (R2 design — empirically fastest): warp per k, 8 q-rows in regs,
//    lane owns u = lane*8..lane*8+7, SHFL tree reduce. Masked k skipped.
//    Grid (LK/128, LQ/8, B) = 512 CTAs, 256 threads.
// ---------------------------------------------------------------------------
__global__ __launch_bounds__(256) void score_kernel(const float* __restrict__ vvec)
{
    int b    = blockIdx.z;
    int q0   = blockIdx.y * 8;
    int k0   = blockIdx.x * 128;
    int vlen = g_vlen[b];
    if (k0 >= vlen) return;
    int kmax = min(k0 + 128, vlen);

    int lane = threadIdx.x & 31;
    int wid  = threadIdx.x >> 5;

    float vr[8];
    {
        float4 a = *(const float4*)(vvec + lane * 8);
        float4 c = *(const float4*)(vvec + lane * 8 + 4);
        vr[0] = a.x; vr[1] = a.y; vr[2] = a.z; vr[3] = a.w;
        vr[4] = c.x; vr[5] = c.y; vr[6] = c.z; vr[7] = c.w;
    }
    float qv[8][8];
    #pragma unroll
    for (int qq = 0; qq < 8; qq++) {
        const float* qr = g_qp + (size_t)(b * LQ + q0 + qq) * UNITS + lane * 8;
        float4 a = *(const float4*)qr;
        float4 c = *(const float4*)(qr + 4);
        qv[qq][0] = a.x; qv[qq][1] = a.y; qv[qq][2] = a.z; qv[qq][3] = a.w;
        qv[qq][4] = c.x; qv[qq][5] = c.y; qv[qq][6] = c.z; qv[qq][7] = c.w;
    }

    const float* kpb = g_kp + (size_t)b * LK * UNITS;
    float*       scb = g_sc + (size_t)(b * LQ + q0) * LK;

    for (int k = k0 + wid; k < kmax; k += 8) {
        const float* kr = kpb + (size_t)k * UNITS + lane * 8;
        float4 ka = *(const float4*)kr;
        float4 kb = *(const float4*)(kr + 4);
        float kv[8] = {ka.x, ka.y, ka.z, ka.w, kb.x, kb.y, kb.z, kb.w};

        float s[8] = {0.f, 0.f, 0.f, 0.f, 0.f, 0.f, 0.f, 0.f};
        #pragma unroll
        for (int j = 0; j < 8; j++) {
            float kj = kv[j];
            float vj = vr[j];
            #pragma unroll
            for (int qq = 0; qq < 8; qq++)
                s[qq] = fmaf(vj, tanh_fast(qv[qq][j] + kj), s[qq]);
        }
        #pragma unroll
        for (int qq = 0; qq < 8; qq++) {
            float v = s[qq];
            #pragma unroll
            for (int off = 16; off > 0; off >>= 1)
                v += __shfl_xor_sync(0xFFFFFFFFu, v, off);
            if (lane == 0) scb[(size_t)qq * LK + k] = v;
        }
    }
}

// ---------------------------------------------------------------------------
// 3) Fused softmax + output GEMM (unchanged — 32q x 64v per CTA).
// ---------------------------------------------------------------------------
__global__ __launch_bounds__(256) void out_kernel(
    const float* __restrict__ value, float* __restrict__ out)
{
    __shared__ float As[32][34];
    __shared__ float Bs[32][64];
    __shared__ float rmax[32], rinv[32];

    int b    = blockIdx.z;
    int m0   = blockIdx.x * 32;
    int n0   = blockIdx.y * 64;
    int vlen = g_vlen[b];
    int kend = (vlen + 31) & ~31;

    const float* S = g_sc  + (size_t)(b * LQ + m0) * LK;
    const float* V = value + (size_t)b * LK * DV;

    int tid  = threadIdx.x;
    int lane = tid & 31;
    int wid  = tid >> 5;

    for (int r = wid; r < 32; r += 8) {
        const float* srow = S + (size_t)r * LK;
        float m = -3.0e38f;
        for (int k = lane; k < vlen; k += 32) m = fmaxf(m, srow[k]);
        #pragma unroll
        for (int off = 16; off > 0; off >>= 1)
            m = fmaxf(m, __shfl_xor_sync(0xFFFFFFFFu, m, off));
        float s = 0.f;
        for (int k = lane; k < vlen; k += 32) s += __expf(srow[k] - m);
        #pragma unroll
        for (int off = 16; off > 0; off >>= 1)
            s += __shfl_xor_sync(0xFFFFFFFFu, s, off);
        if (lane == 0) { rmax[r] = m; rinv[r] = 1.0f / s; }
    }
    __syncthreads();

    int ty = tid >> 4, tx = tid & 15;
    int am = tid >> 3, ak = (tid & 7) * 4;
    int bk = tid >> 3, bn = (tid & 7) * 8;

    ull acc[2][2] = {};

    for (int k0 = 0; k0 < kend; k0 += 32) {
        float4 sv = *(const float4*)(S + (size_t)am * LK + k0 + ak);
        float mr = rmax[am];
        int kg = k0 + ak;
        As[ak + 0][am] = (kg + 0 < vlen) ? __expf(sv.x - mr) : 0.f;
        As[ak + 1][am] = (kg + 1 < vlen) ? __expf(sv.y - mr) : 0.f;
        As[ak + 2][am] = (kg + 2 < vlen) ? __expf(sv.z - mr) : 0.f;
        As[ak + 3][am] = (kg + 3 < vlen) ? __expf(sv.w - mr) : 0.f;

        const float* vp = V + (size_t)(k0 + bk) * DV + n0 + bn;
        *(float4*)&Bs[bk][bn]     = *(const float4*)(vp);
        *(float4*)&Bs[bk][bn + 4] = *(const float4*)(vp + 4);
        __syncthreads();

        #pragma unroll
        for (int kk = 0; kk < 32; kk++) {
            float2 af = *(const float2*)&As[kk][ty * 2];
            ull ap0 = dup2(af.x);
            ull ap1 = dup2(af.y);
            longlong2 bv = *(const longlong2*)&Bs[kk][tx * 4];
            acc[0][0] = ffma2(ap0, (ull)bv.x, acc[0][0]);
            acc[0][1] = ffma2(ap0, (ull)bv.y, acc[0][1]);
            acc[1][0] = ffma2(ap1, (ull)bv.x, acc[1][0]);
            acc[1][1] = ffma2(ap1, (ull)bv.y, acc[1][1]);
        }
        __syncthreads();
    }

    #pragma unroll
    for (int i = 0; i < 2; i++) {
        int r = ty * 2 + i;
        float inv = rinv[r];
        float2 r0 = unpack2(acc[i][0]);
        float2 r1 = unpack2(acc[i][1]);
        *(float4*)(out + (size_t)(b * LQ + m0 + r) * DV + n0 + tx * 4) =
            make_float4(r0.x * inv, r0.y * inv, r1.x * inv, r1.y * inv);
    }
}

// ---------------------------------------------------------------------------
// kernel_launch — inputs: query, key, value, valid_len, W_q, W_k, v
// ---------------------------------------------------------------------------
extern "C" void kernel_launch(void* const* d_in, const int* in_sizes, int n_in,
                              void* d_out, int out_size)
{
    const float* query = (const float*)d_in[0];
    const float* key   = (const float*)d_in[1];
    const float* value = (const float*)d_in[2];
    const void*  vlen  = d_in[3];
    const float* W_q   = (const float*)d_in[4];
    const float* W_k   = (const float*)d_in[5];
    const float* vvec  = (const float*)d_in[6];
    float* out = (float*)d_out;

    // 1) fused q+k projection: 72 x 4 = 288 CTAs, 128 thr (2 CTAs/SM)
    proj_kernel<<<dim3((B * LQ + B * LK) / 64, UNITS / 64), 128>>>(
        query, key, W_q, W_k, vlen);

    // 2) scores: 8 x 16 x 4 = 512 CTAs, 256 thr (masked tiles exit)
    score_kernel<<<dim3(LK / 128, LQ / 8, B), 256>>>(vvec);

    // 3) fused softmax + output GEMM: 4 x 8 x 4 = 128 CTAs
    out_kernel<<<dim3(LQ / 32, DV / 64, B), 256>>>(value, out);
}

// round 6
// speedup vs baseline: 1.2855x; 1.0245x over previous
#include <cuda_runtime.h>
#include <cuda_bf16.h>

#define B     4
#define LQ    128
#define LK    1024
#define D     512
#define DV    512
#define UNITS 256

typedef unsigned long long ull;

// Scratch (device globals — no allocation allowed)
__device__ float g_qp[B * LQ * UNITS];         // [b*LQ+q][u]
__device__ float g_kp[B * LK * UNITS];         // [b*LK+k][u]
__device__ float g_sc[B * LQ * LK];            // raw scores (unmasked region)
__device__ int   g_vlen[B];

__device__ __forceinline__ float tanh_fast(float x) {
    float y;
    asm("tanh.approx.f32 %0, %1;" : "=f"(y) : "f"(x));
    return y;
}
__device__ __forceinline__ ull ffma2(ull a, ull b, ull c) {
    ull d;
    asm("fma.rn.f32x2 %0, %1, %2, %3;" : "=l"(d) : "l"(a), "l"(b), "l"(c));
    return d;
}
__device__ __forceinline__ ull dup2(float x) {
    ull r;
    asm("mov.b64 %0, {%1, %1};" : "=l"(r) : "f"(x));
    return r;
}
__device__ __forceinline__ float2 unpack2(ull v) {
    float2 f;
    asm("mov.b64 {%0, %1}, %2;" : "=f"(f.x), "=f"(f.y) : "l"(v));
    return f;
}

// ---------------------------------------------------------------------------
// 1) Fused projection GEMM (+ vlen decode + per-batch masked-k-tile skip).
//    rows [0,512): g_qp = query @ Wq^T ; rows [512,4608): g_kp = key @ Wk^T
//    CTA 64m x 64n, 256 threads, thread tile 4x4 (8 FFMA2/kk),
//    double-buffered smem. Grid 72 x 4 = 288 CTAs, 16 warps/SM.
// ---------------------------------------------------------------------------
__global__ __launch_bounds__(256) void proj_kernel(
    const float* __restrict__ query, const float* __restrict__ key,
    const float* __restrict__ Wq,    const float* __restrict__ Wk,
    const void*  __restrict__ vl)
{
    // uniform vlen decode (every CTA computes it locally; CTA(0,0) publishes)
    const long long* l = (const long long*)vl;
    const int*       w = (const int*)vl;
    bool ok64 = true;
    #pragma unroll
    for (int i = 0; i < B; i++) {
        long long x = l[i];
        if (x < 1 || x > LK) ok64 = false;
    }
    if (blockIdx.x == 0 && blockIdx.y == 0 && threadIdx.x == 0) {
        #pragma unroll
        for (int i = 0; i < B; i++) g_vlen[i] = ok64 ? (int)l[i] : w[i];
    }

    int mg = blockIdx.x * 64;
    int n0 = blockIdx.y * 64;
    bool is_q = (mg < B * LQ);

    const float *X, *W;
    float* Y;
    int m0;
    if (is_q) { X = query; W = Wq; Y = g_qp; m0 = mg; }
    else {
        m0 = mg - B * LQ;
        int bb = m0 >> 10;
        int krow = m0 & 1023;
        int vb = ok64 ? (int)l[bb] : w[bb];
        if (krow >= vb) return;          // tile fully masked downstream
        X = key; W = Wk; Y = g_kp;
    }

    __shared__ float As[2][16][68];      // [k][m], pad 68
    __shared__ float Bs[2][16][68];      // [k][n], pad 68

    int tid = threadIdx.x;
    int tm  = tid >> 4;                  // 0..15 -> rows tm*4
    int tn  = tid & 15;                  // 0..15 -> cols tn*4

    // staging: thread owns one float4 (row sr, k-offset sk4) of each tile
    int sr  = tid >> 2;                  // 0..63
    int sk4 = (tid & 3) * 4;             // 0,4,8,12
    const float* xrow = X + (size_t)(m0 + sr) * D + sk4;
    const float* wrow = W + (size_t)(n0 + sr) * D + sk4;

    float4 xr = *(const float4*)(xrow);
    float4 wr = *(const float4*)(wrow);
    {
        As[0][sk4 + 0][sr] = xr.x;  Bs[0][sk4 + 0][sr] = wr.x;
        As[0][sk4 + 1][sr] = xr.y;  Bs[0][sk4 + 1][sr] = wr.y;
        As[0][sk4 + 2][sr] = xr.z;  Bs[0][sk4 + 2][sr] = wr.z;
        As[0][sk4 + 3][sr] = xr.w;  Bs[0][sk4 + 3][sr] = wr.w;
    }
    __syncthreads();

    ull acc[4][2] = {};

    const int NT = D / 16;               // 32 k-tiles
    for (int t = 0; t < NT; t++) {
        int buf = t & 1;
        if (t + 1 < NT) {
            xr = *(const float4*)(xrow + (t + 1) * 16);
            wr = *(const float4*)(wrow + (t + 1) * 16);
        }

        #pragma unroll
        for (int kk = 0; kk < 16; kk++) {
            float4 av = *(const float4*)&As[buf][kk][tm * 4];
            longlong2 bv = *(const longlong2*)&Bs[buf][kk][tn * 4];
            ull aa[4];
            aa[0] = dup2(av.x); aa[1] = dup2(av.y);
            aa[2] = dup2(av.z); aa[3] = dup2(av.w);
            #pragma unroll
            for (int i = 0; i < 4; i++) {
                acc[i][0] = ffma2(aa[i], (ull)bv.x, acc[i][0]);
                acc[i][1] = ffma2(aa[i], (ull)bv.y, acc[i][1]);
            }
        }

        if (t + 1 < NT) {
            int nb = buf ^ 1;
            As[nb][sk4 + 0][sr] = xr.x;  Bs[nb][sk4 + 0][sr] = wr.x;
            As[nb][sk4 + 1][sr] = xr.y;  Bs[nb][sk4 + 1][sr] = wr.y;
            As[nb][sk4 + 2][sr] = xr.z;  Bs[nb][sk4 + 2][sr] = wr.z;
            As[nb][sk4 + 3][sr] = xr.w;  Bs[nb][sk4 + 3][sr] = wr.w;
        }
        __syncthreads();
    }

    #pragma unroll
    for (int i = 0; i < 4; i++) {
        float2 r0 = unpack2(acc[i][0]);
        float2 r1 = unpack2(acc[i][1]);
        *(float4*)(Y + (size_t)(m0 + tm * 4 + i) * UNITS + n0 + tn * 4) =
            make_float4(r0.x, r0.y, r1.x, r1.y);
    }
}

// ---------------------------------------------------------------------------
// 2) Scores (R2 design — empirically fastest): warp per k, 8 q-rows in regs,
//    lane owns u = lane*8..lane*8+7, SHFL tree reduce. Masked k skipped.
//    Grid (LK/128, LQ/8, B) = 512 CTAs, 256 threads.
// ---------------------------------------------------------------------------
__global__ __launch_bounds__(256) void score_kernel(const float* __restrict__ vvec)
{
    int b    = blockIdx.z;
    int q0   = blockIdx.y * 8;
    int k0   = blockIdx.x * 128;
    int vlen = g_vlen[b];
    if (k0 >= vlen) return;
    int kmax = min(k0 + 128, vlen);

    int lane = threadIdx.x & 31;
    int wid  = threadIdx.x >> 5;

    float vr[8];
    {
        float4 a = *(const float4*)(vvec + lane * 8);
        float4 c = *(const float4*)(vvec + lane * 8 + 4);
        vr[0] = a.x; vr[1] = a.y; vr[2] = a.z; vr[3] = a.w;
        vr[4] = c.x; vr[5] = c.y; vr[6] = c.z; vr[7] = c.w;
    }
    float qv[8][8];
    #pragma unroll
    for (int qq = 0; qq < 8; qq++) {
        const float* qr = g_qp + (size_t)(b * LQ + q0 + qq) * UNITS + lane * 8;
        float4 a = *(const float4*)qr;
        float4 c = *(const float4*)(qr + 4);
        qv[qq][0] = a.x; qv[qq][1] = a.y; qv[qq][2] = a.z; qv[qq][3] = a.w;
        qv[qq][4] = c.x; qv[qq][5] = c.y; qv[qq][6] = c.z; qv[qq][7] = c.w;
    }

    const float* kpb = g_kp + (size_t)b * LK * UNITS;
    float*       scb = g_sc + (size_t)(b * LQ + q0) * LK;

    for (int k = k0 + wid; k < kmax; k += 8) {
        const float* kr = kpb + (size_t)k * UNITS + lane * 8;
        float4 ka = *(const float4*)kr;
        float4 kb = *(const float4*)(kr + 4);
        float kv[8] = {ka.x, ka.y, ka.z, ka.w, kb.x, kb.y, kb.z, kb.w};

        float s[8] = {0.f, 0.f, 0.f, 0.f, 0.f, 0.f, 0.f, 0.f};
        #pragma unroll
        for (int j = 0; j < 8; j++) {
            float kj = kv[j];
            float vj = vr[j];
            #pragma unroll
            for (int qq = 0; qq < 8; qq++)
                s[qq] = fmaf(vj, tanh_fast(qv[qq][j] + kj), s[qq]);
        }
        #pragma unroll
        for (int qq = 0; qq < 8; qq++) {
            float v = s[qq];
            #pragma unroll
            for (int off = 16; off > 0; off >>= 1)
                v += __shfl_xor_sync(0xFFFFFFFFu, v, off);
            if (lane == 0) scb[(size_t)qq * LK + k] = v;
        }
    }
}

// ---------------------------------------------------------------------------
// 3) Fused softmax + output GEMM (unchanged — 32q x 64v per CTA).
// ---------------------------------------------------------------------------
__global__ __launch_bounds__(256) void out_kernel(
    const float* __restrict__ value, float* __restrict__ out)
{
    __shared__ float As[32][34];
    __shared__ float Bs[32][64];
    __shared__ float rmax[32], rinv[32];

    int b    = blockIdx.z;
    int m0   = blockIdx.x * 32;
    int n0   = blockIdx.y * 64;
    int vlen = g_vlen[b];
    int kend = (vlen + 31) & ~31;

    const float* S = g_sc  + (size_t)(b * LQ + m0) * LK;
    const float* V = value + (size_t)b * LK * DV;

    int tid  = threadIdx.x;
    int lane = tid & 31;
    int wid  = tid >> 5;

    for (int r = wid; r < 32; r += 8) {
        const float* srow = S + (size_t)r * LK;
        float m = -3.0e38f;
        for (int k = lane; k < vlen; k += 32) m = fmaxf(m, srow[k]);
        #pragma unroll
        for (int off = 16; off > 0; off >>= 1)
            m = fmaxf(m, __shfl_xor_sync(0xFFFFFFFFu, m, off));
        float s = 0.f;
        for (int k = lane; k < vlen; k += 32) s += __expf(srow[k] - m);
        #pragma unroll
        for (int off = 16; off > 0; off >>= 1)
            s += __shfl_xor_sync(0xFFFFFFFFu, s, off);
        if (lane == 0) { rmax[r] = m; rinv[r] = 1.0f / s; }
    }
    __syncthreads();

    int ty = tid >> 4, tx = tid & 15;
    int am = tid >> 3, ak = (tid & 7) * 4;
    int bk = tid >> 3, bn = (tid & 7) * 8;

    ull acc[2][2] = {};

    for (int k0 = 0; k0 < kend; k0 += 32) {
        float4 sv = *(const float4*)(S + (size_t)am * LK + k0 + ak);
        float mr = rmax[am];
        int kg = k0 + ak;
        As[ak + 0][am] = (kg + 0 < vlen) ? __expf(sv.x - mr) : 0.f;
        As[ak + 1][am] = (kg + 1 < vlen) ? __expf(sv.y - mr) : 0.f;
        As[ak + 2][am] = (kg + 2 < vlen) ? __expf(sv.z - mr) : 0.f;
        As[ak + 3][am] = (kg + 3 < vlen) ? __expf(sv.w - mr) : 0.f;

        const float* vp = V + (size_t)(k0 + bk) * DV + n0 + bn;
        *(float4*)&Bs[bk][bn]     = *(const float4*)(vp);
        *(float4*)&Bs[bk][bn + 4] = *(const float4*)(vp + 4);
        __syncthreads();

        #pragma unroll
        for (int kk = 0; kk < 32; kk++) {
            float2 af = *(const float2*)&As[kk][ty * 2];
            ull ap0 = dup2(af.x);
            ull ap1 = dup2(af.y);
            longlong2 bv = *(const longlong2*)&Bs[kk][tx * 4];
            acc[0][0] = ffma2(ap0, (ull)bv.x, acc[0][0]);
            acc[0][1] = ffma2(ap0, (ull)bv.y, acc[0][1]);
            acc[1][0] = ffma2(ap1, (ull)bv.x, acc[1][0]);
            acc[1][1] = ffma2(ap1, (ull)bv.y, acc[1][1]);
        }
        __syncthreads();
    }

    #pragma unroll
    for (int i = 0; i < 2; i++) {
        int r = ty * 2 + i;
        float inv = rinv[r];
        float2 r0 = unpack2(acc[i][0]);
        float2 r1 = unpack2(acc[i][1]);
        *(float4*)(out + (size_t)(b * LQ + m0 + r) * DV + n0 + tx * 4) =
            make_float4(r0.x * inv, r0.y * inv, r1.x * inv, r1.y * inv);
    }
}

// ---------------------------------------------------------------------------
// kernel_launch — inputs: query, key, value, valid_len, W_q, W_k, v
// ---------------------------------------------------------------------------
extern "C" void kernel_launch(void* const* d_in, const int* in_sizes, int n_in,
                              void* d_out, int out_size)
{
    const float* query = (const float*)d_in[0];
    const float* key   = (const float*)d_in[1];
    const float* value = (const float*)d_in[2];
    const void*  vlen  = d_in[3];
    const float* W_q   = (const float*)d_in[4];
    const float* W_k   = (const float*)d_in[5];
    const float* vvec  = (const float*)d_in[6];
    float* out = (float*)d_out;

    // 1) fused q+k projection: 72 x 4 = 288 CTAs, 256 thr
    proj_kernel<<<dim3((B * LQ + B * LK) / 64, UNITS / 64), 256>>>(
        query, key, W_q, W_k, vlen);

    // 2) scores: 8 x 16 x 4 = 512 CTAs, 256 thr (masked tiles exit)
    score_kernel<<<dim3(LK / 128, LQ / 8, B), 256>>>(vvec);

    // 3) fused softmax + output GEMM: 4 x 8 x 4 = 128 CTAs
    out_kernel<<<dim3(LQ / 32, DV / 64, B), 256>>>(value, out);
}

// round 7
// speedup vs baseline: 1.4356x; 1.1167x over previous
#include <cuda_runtime.h>
#include <cuda_bf16.h>

#define B     4
#define LQ    128
#define LK    1024
#define D     512
#define DV    512
#define UNITS 256

typedef unsigned long long ull;

// Scratch (device globals — no allocation allowed)
__device__ float g_qp[B * LQ * UNITS];         // [b*LQ+q][u]
__device__ float g_kp[B * LK * UNITS];         // [b*LK+k][u]
__device__ float g_sc[B * LQ * LK];            // raw scores (unmasked region)
__device__ int   g_vlen[B];

__device__ __forceinline__ float tanh_fast(float x) {
    float y;
    asm("tanh.approx.f32 %0, %1;" : "=f"(y) : "f"(x));
    return y;
}
__device__ __forceinline__ ull ffma2(ull a, ull b, ull c) {
    ull d;
    asm("fma.rn.f32x2 %0, %1, %2, %3;" : "=l"(d) : "l"(a), "l"(b), "l"(c));
    return d;
}
__device__ __forceinline__ ull dup2(float x) {
    ull r;
    asm("mov.b64 %0, {%1, %1};" : "=l"(r) : "f"(x));
    return r;
}
__device__ __forceinline__ float2 unpack2(ull v) {
    float2 f;
    asm("mov.b64 {%0, %1}, %2;" : "=f"(f.x), "=f"(f.y) : "l"(v));
    return f;
}

// ---------------------------------------------------------------------------
// 1) Fused projection GEMM (+ vlen decode + per-batch masked-k-tile skip).
//    CTA 64m x 64n, 256 threads, thread tile 4x4, double-buffered smem,
//    register double-buffer over kk (breaks LDS->use stalls).
// ---------------------------------------------------------------------------
__global__ __launch_bounds__(256) void proj_kernel(
    const float* __restrict__ query, const float* __restrict__ key,
    const float* __restrict__ Wq,    const float* __restrict__ Wk,
    const void*  __restrict__ vl)
{
    const long long* l = (const long long*)vl;
    const int*       w = (const int*)vl;
    bool ok64 = true;
    #pragma unroll
    for (int i = 0; i < B; i++) {
        long long x = l[i];
        if (x < 1 || x > LK) ok64 = false;
    }
    if (blockIdx.x == 0 && blockIdx.y == 0 && threadIdx.x == 0) {
        #pragma unroll
        for (int i = 0; i < B; i++) g_vlen[i] = ok64 ? (int)l[i] : w[i];
    }

    int mg = blockIdx.x * 64;
    int n0 = blockIdx.y * 64;
    bool is_q = (mg < B * LQ);

    const float *X, *W;
    float* Y;
    int m0;
    if (is_q) { X = query; W = Wq; Y = g_qp; m0 = mg; }
    else {
        m0 = mg - B * LQ;
        int bb = m0 >> 10;
        int krow = m0 & 1023;
        int vb = ok64 ? (int)l[bb] : w[bb];
        if (krow >= vb) return;          // tile fully masked downstream
        X = key; W = Wk; Y = g_kp;
    }

    __shared__ float As[2][16][68];      // [k][m]
    __shared__ float Bs[2][16][68];      // [k][n]

    int tid = threadIdx.x;
    int tm  = tid >> 4;                  // rows tm*4
    int tn  = tid & 15;                  // cols tn*4

    int sr  = tid >> 2;                  // 0..63
    int sk4 = (tid & 3) * 4;             // 0,4,8,12
    const float* xrow = X + (size_t)(m0 + sr) * D + sk4;
    const float* wrow = W + (size_t)(n0 + sr) * D + sk4;

    float4 xr = *(const float4*)(xrow);
    float4 wr = *(const float4*)(wrow);
    As[0][sk4 + 0][sr] = xr.x;  Bs[0][sk4 + 0][sr] = wr.x;
    As[0][sk4 + 1][sr] = xr.y;  Bs[0][sk4 + 1][sr] = wr.y;
    As[0][sk4 + 2][sr] = xr.z;  Bs[0][sk4 + 2][sr] = wr.z;
    As[0][sk4 + 3][sr] = xr.w;  Bs[0][sk4 + 3][sr] = wr.w;
    __syncthreads();

    ull acc[4][2] = {};

    const int NT = D / 16;               // 32 k-tiles
    for (int t = 0; t < NT; t++) {
        int buf = t & 1;
        if (t + 1 < NT) {
            xr = *(const float4*)(xrow + (t + 1) * 16);
            wr = *(const float4*)(wrow + (t + 1) * 16);
        }

        // register double-buffer over kk
        float4    av = *(const float4*)&As[buf][0][tm * 4];
        longlong2 bv = *(const longlong2*)&Bs[buf][0][tn * 4];
        #pragma unroll
        for (int kk = 0; kk < 16; kk++) {
            float4    avn;
            longlong2 bvn;
            if (kk < 15) {
                avn = *(const float4*)&As[buf][kk + 1][tm * 4];
                bvn = *(const longlong2*)&Bs[buf][kk + 1][tn * 4];
            }
            ull a0 = dup2(av.x), a1 = dup2(av.y);
            ull a2 = dup2(av.z), a3 = dup2(av.w);
            acc[0][0] = ffma2(a0, (ull)bv.x, acc[0][0]);
            acc[0][1] = ffma2(a0, (ull)bv.y, acc[0][1]);
            acc[1][0] = ffma2(a1, (ull)bv.x, acc[1][0]);
            acc[1][1] = ffma2(a1, (ull)bv.y, acc[1][1]);
            acc[2][0] = ffma2(a2, (ull)bv.x, acc[2][0]);
            acc[2][1] = ffma2(a2, (ull)bv.y, acc[2][1]);
            acc[3][0] = ffma2(a3, (ull)bv.x, acc[3][0]);
            acc[3][1] = ffma2(a3, (ull)bv.y, acc[3][1]);
            av = avn; bv = bvn;
        }

        if (t + 1 < NT) {
            int nb = buf ^ 1;
            As[nb][sk4 + 0][sr] = xr.x;  Bs[nb][sk4 + 0][sr] = wr.x;
            As[nb][sk4 + 1][sr] = xr.y;  Bs[nb][sk4 + 1][sr] = wr.y;
            As[nb][sk4 + 2][sr] = xr.z;  Bs[nb][sk4 + 2][sr] = wr.z;
            As[nb][sk4 + 3][sr] = xr.w;  Bs[nb][sk4 + 3][sr] = wr.w;
        }
        __syncthreads();
    }

    #pragma unroll
    for (int i = 0; i < 4; i++) {
        float2 r0 = unpack2(acc[i][0]);
        float2 r1 = unpack2(acc[i][1]);
        *(float4*)(Y + (size_t)(m0 + tm * 4 + i) * UNITS + n0 + tn * 4) =
            make_float4(r0.x, r0.y, r1.x, r1.y);
    }
}

// ---------------------------------------------------------------------------
// 2) Scores: warp per k, 8 q-rows in regs, lane owns u = lane*8..lane*8+7,
//    SHFL tree reduce. NEW: next-k kp row prefetched into registers before
//    computing the current k (hides ~250cyc L2 latency).
// ---------------------------------------------------------------------------
__global__ __launch_bounds__(256) void score_kernel(const float* __restrict__ vvec)
{
    int b    = blockIdx.z;
    int q0   = blockIdx.y * 8;
    int k0   = blockIdx.x * 128;
    int vlen = g_vlen[b];
    if (k0 >= vlen) return;
    int kmax = min(k0 + 128, vlen);

    int lane = threadIdx.x & 31;
    int wid  = threadIdx.x >> 5;

    float vr[8];
    {
        float4 a = *(const float4*)(vvec + lane * 8);
        float4 c = *(const float4*)(vvec + lane * 8 + 4);
        vr[0] = a.x; vr[1] = a.y; vr[2] = a.z; vr[3] = a.w;
        vr[4] = c.x; vr[5] = c.y; vr[6] = c.z; vr[7] = c.w;
    }
    float qv[8][8];
    #pragma unroll
    for (int qq = 0; qq < 8; qq++) {
        const float* qr = g_qp + (size_t)(b * LQ + q0 + qq) * UNITS + lane * 8;
        float4 a = *(const float4*)qr;
        float4 c = *(const float4*)(qr + 4);
        qv[qq][0] = a.x; qv[qq][1] = a.y; qv[qq][2] = a.z; qv[qq][3] = a.w;
        qv[qq][4] = c.x; qv[qq][5] = c.y; qv[qq][6] = c.z; qv[qq][7] = c.w;
    }

    const float* kpb = g_kp + (size_t)b * LK * UNITS;
    float*       scb = g_sc + (size_t)(b * LQ + q0) * LK;

    int k = k0 + wid;
    if (k >= kmax) return;

    float4 ka, kb;
    {
        const float* kr = kpb + (size_t)k * UNITS + lane * 8;
        ka = *(const float4*)kr;
        kb = *(const float4*)(kr + 4);
    }

    while (k < kmax) {
        int kn = k + 8;
        float4 kan, kbn;
        if (kn < kmax) {
            const float* krn = kpb + (size_t)kn * UNITS + lane * 8;
            kan = *(const float4*)krn;
            kbn = *(const float4*)(krn + 4);
        }

        float kv[8] = {ka.x, ka.y, ka.z, ka.w, kb.x, kb.y, kb.z, kb.w};
        float s[8] = {0.f, 0.f, 0.f, 0.f, 0.f, 0.f, 0.f, 0.f};
        #pragma unroll
        for (int j = 0; j < 8; j++) {
            float kj = kv[j];
            float vj = vr[j];
            #pragma unroll
            for (int qq = 0; qq < 8; qq++)
                s[qq] = fmaf(vj, tanh_fast(qv[qq][j] + kj), s[qq]);
        }
        #pragma unroll
        for (int qq = 0; qq < 8; qq++) {
            float v = s[qq];
            #pragma unroll
            for (int off = 16; off > 0; off >>= 1)
                v += __shfl_xor_sync(0xFFFFFFFFu, v, off);
            if (lane == 0) scb[(size_t)qq * LK + k] = v;
        }

        ka = kan; kb = kbn;
        k = kn;
    }
}

// ---------------------------------------------------------------------------
// 3) Fused softmax + output GEMM (unchanged — 32q x 64v per CTA).
// ---------------------------------------------------------------------------
__global__ __launch_bounds__(256) void out_kernel(
    const float* __restrict__ value, float* __restrict__ out)
{
    __shared__ float As[32][34];
    __shared__ float Bs[32][64];
    __shared__ float rmax[32], rinv[32];

    int b    = blockIdx.z;
    int m0   = blockIdx.x * 32;
    int n0   = blockIdx.y * 64;
    int vlen = g_vlen[b];
    int kend = (vlen + 31) & ~31;

    const float* S = g_sc  + (size_t)(b * LQ + m0) * LK;
    const float* V = value + (size_t)b * LK * DV;

    int tid  = threadIdx.x;
    int lane = tid & 31;
    int wid  = tid >> 5;

    for (int r = wid; r < 32; r += 8) {
        const float* srow = S + (size_t)r * LK;
        float m = -3.0e38f;
        for (int k = lane; k < vlen; k += 32) m = fmaxf(m, srow[k]);
        #pragma unroll
        for (int off = 16; off > 0; off >>= 1)
            m = fmaxf(m, __shfl_xor_sync(0xFFFFFFFFu, m, off));
        float s = 0.f;
        for (int k = lane; k < vlen; k += 32) s += __expf(srow[k] - m);
        #pragma unroll
        for (int off = 16; off > 0; off >>= 1)
            s += __shfl_xor_sync(0xFFFFFFFFu, s, off);
        if (lane == 0) { rmax[r] = m; rinv[r] = 1.0f / s; }
    }
    __syncthreads();

    int ty = tid >> 4, tx = tid & 15;
    int am = tid >> 3, ak = (tid & 7) * 4;
    int bk = tid >> 3, bn = (tid & 7) * 8;

    ull acc[2][2] = {};

    for (int k0 = 0; k0 < kend; k0 += 32) {
        float4 sv = *(const float4*)(S + (size_t)am * LK + k0 + ak);
        float mr = rmax[am];
        int kg = k0 + ak;
        As[ak + 0][am] = (kg + 0 < vlen) ? __expf(sv.x - mr) : 0.f;
        As[ak + 1][am] = (kg + 1 < vlen) ? __expf(sv.y - mr) : 0.f;
        As[ak + 2][am] = (kg + 2 < vlen) ? __expf(sv.z - mr) : 0.f;
        As[ak + 3][am] = (kg + 3 < vlen) ? __expf(sv.w - mr) : 0.f;

        const float* vp = V + (size_t)(k0 + bk) * DV + n0 + bn;
        *(float4*)&Bs[bk][bn]     = *(const float4*)(vp);
        *(float4*)&Bs[bk][bn + 4] = *(const float4*)(vp + 4);
        __syncthreads();

        #pragma unroll
        for (int kk = 0; kk < 32; kk++) {
            float2 af = *(const float2*)&As[kk][ty * 2];
            ull ap0 = dup2(af.x);
            ull ap1 = dup2(af.y);
            longlong2 bv = *(const longlong2*)&Bs[kk][tx * 4];
            acc[0][0] = ffma2(ap0, (ull)bv.x, acc[0][0]);
            acc[0][1] = ffma2(ap0, (ull)bv.y, acc[0][1]);
            acc[1][0] = ffma2(ap1, (ull)bv.x, acc[1][0]);
            acc[1][1] = ffma2(ap1, (ull)bv.y, acc[1][1]);
        }
        __syncthreads();
    }

    #pragma unroll
    for (int i = 0; i < 2; i++) {
        int r = ty * 2 + i;
        float inv = rinv[r];
        float2 r0 = unpack2(acc[i][0]);
        float2 r1 = unpack2(acc[i][1]);
        *(float4*)(out + (size_t)(b * LQ + m0 + r) * DV + n0 + tx * 4) =
            make_float4(r0.x * inv, r0.y * inv, r1.x * inv, r1.y * inv);
    }
}

// ---------------------------------------------------------------------------
// kernel_launch — inputs: query, key, value, valid_len, W_q, W_k, v
// ---------------------------------------------------------------------------
extern "C" void kernel_launch(void* const* d_in, const int* in_sizes, int n_in,
                              void* d_out, int out_size)
{
    const float* query = (const float*)d_in[0];
    const float* key   = (const float*)d_in[1];
    const float* value = (const float*)d_in[2];
    const void*  vlen  = d_in[3];
    const float* W_q   = (const float*)d_in[4];
    const float* W_k   = (const float*)d_in[5];
    const float* vvec  = (const float*)d_in[6];
    float* out = (float*)d_out;

    // 1) fused q+k projection: 72 x 4 = 288 CTAs, 256 thr
    proj_kernel<<<dim3((B * LQ + B * LK) / 64, UNITS / 64), 256>>>(
        query, key, W_q, W_k, vlen);

    // 2) scores: 8 x 16 x 4 = 512 CTAs, 256 thr (masked tiles exit)
    score_kernel<<<dim3(LK / 128, LQ / 8, B), 256>>>(vvec);

    // 3) fused softmax + output GEMM: 4 x 8 x 4 = 128 CTAs
    out_kernel<<<dim3(LQ / 32, DV / 64, B), 256>>>(value, out);
}

// round 8
// speedup vs baseline: 1.6065x; 1.1191x over previous
#include <cuda_runtime.h>
#include <cuda_bf16.h>
#include <stdint.h>

#define B     4
#define LQ    128
#define LK    1024
#define D     512
#define DV    512
#define UNITS 256

typedef unsigned long long ull;

// Scratch (device globals — no allocation allowed)
__device__ float g_qp[B * LQ * UNITS];         // [b*LQ+q][u]
__device__ float g_kp[B * LK * UNITS];         // [b*LK+k][u]
__device__ float g_sc[B * LQ * LK];            // raw scores (unmasked region)
__device__ int   g_vlen[B];

__device__ __forceinline__ float tanh_fast(float x) {
    float y;
    asm("tanh.approx.f32 %0, %1;" : "=f"(y) : "f"(x));
    return y;
}
__device__ __forceinline__ ull ffma2(ull a, ull b, ull c) {
    ull d;
    asm("fma.rn.f32x2 %0, %1, %2, %3;" : "=l"(d) : "l"(a), "l"(b), "l"(c));
    return d;
}
__device__ __forceinline__ ull dup2(float x) {
    ull r;
    asm("mov.b64 %0, {%1, %1};" : "=l"(r) : "f"(x));
    return r;
}
__device__ __forceinline__ float2 unpack2(ull v) {
    float2 f;
    asm("mov.b64 {%0, %1}, %2;" : "=f"(f.x), "=f"(f.y) : "l"(v));
    return f;
}
__device__ __forceinline__ uint32_t to_tf32(float x) {
    uint32_t r;
    asm("cvt.rna.tf32.f32 %0, %1;" : "=r"(r) : "f"(x));
    return r;
}
__device__ __forceinline__ void mma_tf32(
    float& d0, float& d1, float& d2, float& d3,
    uint32_t a0, uint32_t a1, uint32_t a2, uint32_t a3,
    uint32_t b0, uint32_t b1)
{
    asm("mma.sync.aligned.m16n8k8.row.col.f32.tf32.tf32.f32 "
        "{%0,%1,%2,%3}, {%4,%5,%6,%7}, {%8,%9}, {%0,%1,%2,%3};"
        : "+f"(d0), "+f"(d1), "+f"(d2), "+f"(d3)
        : "r"(a0), "r"(a1), "r"(a2), "r"(a3), "r"(b0), "r"(b1));
}

#define PADK 20   // 16 k-cols padded to 20 -> fragment LDS is bank-conflict-free

// ---------------------------------------------------------------------------
// 1) Projection GEMM via tf32 mma.sync (+ vlen decode + masked-k-tile skip).
//    rows [0,512): g_qp = query @ Wq^T ; rows [512,4608): g_kp = key @ Wk^T
//    CTA 64m x 64n, 256 threads = 8 warps (2m x 4n), warp tile 32m x 16n,
//    4 mma(m16n8k8) per warp per k8. Smem tiles [row][k] pad 20, dbl-buffered.
// ---------------------------------------------------------------------------
__global__ __launch_bounds__(256) void proj_kernel(
    const float* __restrict__ query, const float* __restrict__ key,
    const float* __restrict__ Wq,    const float* __restrict__ Wk,
    const void*  __restrict__ vl)
{
    const long long* l = (const long long*)vl;
    const int*       w = (const int*)vl;
    bool ok64 = true;
    #pragma unroll
    for (int i = 0; i < B; i++) {
        long long x = l[i];
        if (x < 1 || x > LK) ok64 = false;
    }
    if (blockIdx.x == 0 && blockIdx.y == 0 && threadIdx.x == 0) {
        #pragma unroll
        for (int i = 0; i < B; i++) g_vlen[i] = ok64 ? (int)l[i] : w[i];
    }

    int mg = blockIdx.x * 64;
    int n0 = blockIdx.y * 64;
    bool is_q = (mg < B * LQ);

    const float *X, *W;
    float* Y;
    int m0;
    if (is_q) { X = query; W = Wq; Y = g_qp; m0 = mg; }
    else {
        m0 = mg - B * LQ;
        int bb = m0 >> 10;
        int krow = m0 & 1023;
        int vb = ok64 ? (int)l[bb] : w[bb];
        if (krow >= vb) return;          // tile fully masked downstream
        X = key; W = Wk; Y = g_kp;
    }

    __shared__ uint32_t As[2][64][PADK];   // A tile [m][k] (tf32 bits)
    __shared__ uint32_t Bs[2][64][PADK];   // W tile [n][k] (tf32 bits)

    int tid  = threadIdx.x;
    int lane = tid & 31;
    int wrp  = tid >> 5;
    int warpM = wrp >> 2;                  // 0..1 -> rows warpM*32
    int warpN = wrp & 3;                   // 0..3 -> cols warpN*16
    int g  = lane >> 2;                    // groupID 0..7
    int t4 = lane & 3;                     // threadID-in-group 0..3

    // staging: thread owns float4 at (row sr, k-offset sk4)
    int sr  = tid >> 2;                    // 0..63
    int sk4 = (tid & 3) * 4;               // 0,4,8,12
    const float* xrow = X + (size_t)(m0 + sr) * D + sk4;
    const float* wrow = W + (size_t)(n0 + sr) * D + sk4;

    float4 xr = *(const float4*)(xrow);
    float4 wr = *(const float4*)(wrow);
    As[0][sr][sk4 + 0] = to_tf32(xr.x);  Bs[0][sr][sk4 + 0] = to_tf32(wr.x);
    As[0][sr][sk4 + 1] = to_tf32(xr.y);  Bs[0][sr][sk4 + 1] = to_tf32(wr.y);
    As[0][sr][sk4 + 2] = to_tf32(xr.z);  Bs[0][sr][sk4 + 2] = to_tf32(wr.z);
    As[0][sr][sk4 + 3] = to_tf32(xr.w);  Bs[0][sr][sk4 + 3] = to_tf32(wr.w);
    __syncthreads();

    // acc[f][ni][4]: f = m-subtile (16 rows), ni = n-subtile (8 cols)
    float acc[2][2][4] = {};

    int rm0 = warpM * 32;
    int cn0 = warpN * 16;

    const int NT = D / 16;                 // 32 k16 tiles
    for (int t = 0; t < NT; t++) {
        int buf = t & 1;
        if (t + 1 < NT) {
            xr = *(const float4*)(xrow + (t + 1) * 16);
            wr = *(const float4*)(wrow + (t + 1) * 16);
        }

        #pragma unroll
        for (int k8 = 0; k8 < 16; k8 += 8) {
            uint32_t a[2][4], b[2][2];
            #pragma unroll
            for (int f = 0; f < 2; f++) {
                int r = rm0 + f * 16 + g;
                a[f][0] = As[buf][r][k8 + t4];
                a[f][1] = As[buf][r + 8][k8 + t4];
                a[f][2] = As[buf][r][k8 + t4 + 4];
                a[f][3] = As[buf][r + 8][k8 + t4 + 4];
            }
            #pragma unroll
            for (int ni = 0; ni < 2; ni++) {
                int c = cn0 + ni * 8 + g;
                b[ni][0] = Bs[buf][c][k8 + t4];
                b[ni][1] = Bs[buf][c][k8 + t4 + 4];
            }
            #pragma unroll
            for (int f = 0; f < 2; f++)
                #pragma unroll
                for (int ni = 0; ni < 2; ni++)
                    mma_tf32(acc[f][ni][0], acc[f][ni][1],
                             acc[f][ni][2], acc[f][ni][3],
                             a[f][0], a[f][1], a[f][2], a[f][3],
                             b[ni][0], b[ni][1]);
        }

        if (t + 1 < NT) {
            int nb = buf ^ 1;
            As[nb][sr][sk4 + 0] = to_tf32(xr.x);  Bs[nb][sr][sk4 + 0] = to_tf32(wr.x);
            As[nb][sr][sk4 + 1] = to_tf32(xr.y);  Bs[nb][sr][sk4 + 1] = to_tf32(wr.y);
            As[nb][sr][sk4 + 2] = to_tf32(xr.z);  Bs[nb][sr][sk4 + 2] = to_tf32(wr.z);
            As[nb][sr][sk4 + 3] = to_tf32(xr.w);  Bs[nb][sr][sk4 + 3] = to_tf32(wr.w);
        }
        __syncthreads();
    }

    // epilogue: c0=(g,2t4) c1=(g,2t4+1) c2=(g+8,2t4) c3=(g+8,2t4+1)
    #pragma unroll
    for (int f = 0; f < 2; f++) {
        #pragma unroll
        for (int ni = 0; ni < 2; ni++) {
            int row = m0 + rm0 + f * 16 + g;
            int col = n0 + cn0 + ni * 8 + 2 * t4;
            *(float2*)(Y + (size_t)row * UNITS + col) =
                make_float2(acc[f][ni][0], acc[f][ni][1]);
            *(float2*)(Y + (size_t)(row + 8) * UNITS + col) =
                make_float2(acc[f][ni][2], acc[f][ni][3]);
        }
    }
}

// ---------------------------------------------------------------------------
// 2) Scores: warp per k, 8 q-rows in regs, next-k prefetch (unchanged R7).
// ---------------------------------------------------------------------------
__global__ __launch_bounds__(256) void score_kernel(const float* __restrict__ vvec)
{
    int b    = blockIdx.z;
    int q0   = blockIdx.y * 8;
    int k0   = blockIdx.x * 128;
    int vlen = g_vlen[b];
    if (k0 >= vlen) return;
    int kmax = min(k0 + 128, vlen);

    int lane = threadIdx.x & 31;
    int wid  = threadIdx.x >> 5;

    float vr[8];
    {
        float4 a = *(const float4*)(vvec + lane * 8);
        float4 c = *(const float4*)(vvec + lane * 8 + 4);
        vr[0] = a.x; vr[1] = a.y; vr[2] = a.z; vr[3] = a.w;
        vr[4] = c.x; vr[5] = c.y; vr[6] = c.z; vr[7] = c.w;
    }
    float qv[8][8];
    #pragma unroll
    for (int qq = 0; qq < 8; qq++) {
        const float* qr = g_qp + (size_t)(b * LQ + q0 + qq) * UNITS + lane * 8;
        float4 a = *(const float4*)qr;
        float4 c = *(const float4*)(qr + 4);
        qv[qq][0] = a.x; qv[qq][1] = a.y; qv[qq][2] = a.z; qv[qq][3] = a.w;
        qv[qq][4] = c.x; qv[qq][5] = c.y; qv[qq][6] = c.z; qv[qq][7] = c.w;
    }

    const float* kpb = g_kp + (size_t)b * LK * UNITS;
    float*       scb = g_sc + (size_t)(b * LQ + q0) * LK;

    int k = k0 + wid;
    if (k >= kmax) return;

    float4 ka, kb;
    {
        const float* kr = kpb + (size_t)k * UNITS + lane * 8;
        ka = *(const float4*)kr;
        kb = *(const float4*)(kr + 4);
    }

    while (k < kmax) {
        int kn = k + 8;
        float4 kan, kbn;
        if (kn < kmax) {
            const float* krn = kpb + (size_t)kn * UNITS + lane * 8;
            kan = *(const float4*)krn;
            kbn = *(const float4*)(krn + 4);
        }

        float kv[8] = {ka.x, ka.y, ka.z, ka.w, kb.x, kb.y, kb.z, kb.w};
        float s[8] = {0.f, 0.f, 0.f, 0.f, 0.f, 0.f, 0.f, 0.f};
        #pragma unroll
        for (int j = 0; j < 8; j++) {
            float kj = kv[j];
            float vj = vr[j];
            #pragma unroll
            for (int qq = 0; qq < 8; qq++)
                s[qq] = fmaf(vj, tanh_fast(qv[qq][j] + kj), s[qq]);
        }
        #pragma unroll
        for (int qq = 0; qq < 8; qq++) {
            float v = s[qq];
            #pragma unroll
            for (int off = 16; off > 0; off >>= 1)
                v += __shfl_xor_sync(0xFFFFFFFFu, v, off);
            if (lane == 0) scb[(size_t)qq * LK + k] = v;
        }

        ka = kan; kb = kbn;
        k = kn;
    }
}

// ---------------------------------------------------------------------------
// 3) Fused softmax + output GEMM (unchanged).
// ---------------------------------------------------------------------------
__global__ __launch_bounds__(256) void out_kernel(
    const float* __restrict__ value, float* __restrict__ out)
{
    __shared__ float As[32][34];
    __shared__ float Bs[32][64];
    __shared__ float rmax[32], rinv[32];

    int b    = blockIdx.z;
    int m0   = blockIdx.x * 32;
    int n0   = blockIdx.y * 64;
    int vlen = g_vlen[b];
    int kend = (vlen + 31) & ~31;

    const float* S = g_sc  + (size_t)(b * LQ + m0) * LK;
    const float* V = value + (size_t)b * LK * DV;

    int tid  = threadIdx.x;
    int lane = tid & 31;
    int wid  = tid >> 5;

    for (int r = wid; r < 32; r += 8) {
        const float* srow = S + (size_t)r * LK;
        float m = -3.0e38f;
        for (int k = lane; k < vlen; k += 32) m = fmaxf(m, srow[k]);
        #pragma unroll
        for (int off = 16; off > 0; off >>= 1)
            m = fmaxf(m, __shfl_xor_sync(0xFFFFFFFFu, m, off));
        float s = 0.f;
        for (int k = lane; k < vlen; k += 32) s += __expf(srow[k] - m);
        #pragma unroll
        for (int off = 16; off > 0; off >>= 1)
            s += __shfl_xor_sync(0xFFFFFFFFu, s, off);
        if (lane == 0) { rmax[r] = m; rinv[r] = 1.0f / s; }
    }
    __syncthreads();

    int ty = tid >> 4, tx = tid & 15;
    int am = tid >> 3, ak = (tid & 7) * 4;
    int bk = tid >> 3, bn = (tid & 7) * 8;

    ull acc[2][2] = {};

    for (int k0 = 0; k0 < kend; k0 += 32) {
        float4 sv = *(const float4*)(S + (size_t)am * LK + k0 + ak);
        float mr = rmax[am];
        int kg = k0 + ak;
        As[ak + 0][am] = (kg + 0 < vlen) ? __expf(sv.x - mr) : 0.f;
        As[ak + 1][am] = (kg + 1 < vlen) ? __expf(sv.y - mr) : 0.f;
        As[ak + 2][am] = (kg + 2 < vlen) ? __expf(sv.z - mr) : 0.f;
        As[ak + 3][am] = (kg + 3 < vlen) ? __expf(sv.w - mr) : 0.f;

        const float* vp = V + (size_t)(k0 + bk) * DV + n0 + bn;
        *(float4*)&Bs[bk][bn]     = *(const float4*)(vp);
        *(float4*)&Bs[bk][bn + 4] = *(const float4*)(vp + 4);
        __syncthreads();

        #pragma unroll
        for (int kk = 0; kk < 32; kk++) {
            float2 af = *(const float2*)&As[kk][ty * 2];
            ull ap0 = dup2(af.x);
            ull ap1 = dup2(af.y);
            longlong2 bv = *(const longlong2*)&Bs[kk][tx * 4];
            acc[0][0] = ffma2(ap0, (ull)bv.x, acc[0][0]);
            acc[0][1] = ffma2(ap0, (ull)bv.y, acc[0][1]);
            acc[1][0] = ffma2(ap1, (ull)bv.x, acc[1][0]);
            acc[1][1] = ffma2(ap1, (ull)bv.y, acc[1][1]);
        }
        __syncthreads();
    }

    #pragma unroll
    for (int i = 0; i < 2; i++) {
        int r = ty * 2 + i;
        float inv = rinv[r];
        float2 r0 = unpack2(acc[i][0]);
        float2 r1 = unpack2(acc[i][1]);
        *(float4*)(out + (size_t)(b * LQ + m0 + r) * DV + n0 + tx * 4) =
            make_float4(r0.x * inv, r0.y * inv, r1.x * inv, r1.y * inv);
    }
}

// ---------------------------------------------------------------------------
// kernel_launch — inputs: query, key, value, valid_len, W_q, W_k, v
// ---------------------------------------------------------------------------
extern "C" void kernel_launch(void* const* d_in, const int* in_sizes, int n_in,
                              void* d_out, int out_size)
{
    const float* query = (const float*)d_in[0];
    const float* key   = (const float*)d_in[1];
    const float* value = (const float*)d_in[2];
    const void*  vlen  = d_in[3];
    const float* W_q   = (const float*)d_in[4];
    const float* W_k   = (const float*)d_in[5];
    const float* vvec  = (const float*)d_in[6];
    float* out = (float*)d_out;

    // 1) fused q+k projection via tf32 mma: 72 x 4 = 288 CTAs, 256 thr
    proj_kernel<<<dim3((B * LQ + B * LK) / 64, UNITS / 64), 256>>>(
        query, key, W_q, W_k, vlen);

    // 2) scores: 8 x 16 x 4 = 512 CTAs, 256 thr (masked tiles exit)
    score_kernel<<<dim3(LK / 128, LQ / 8, B), 256>>>(vvec);

    // 3) fused softmax + output GEMM: 4 x 8 x 4 = 128 CTAs
    out_kernel<<<dim3(LQ / 32, DV / 64, B), 256>>>(value, out);
}